// round 16
// baseline (speedup 1.0000x reference)
#include <cuda_runtime.h>

#define HH    136
#define WWW   200
#define HW    (HH*WWW)
#define OH    272
#define OW    400
#define NIMG  8
#define NINST 512
#define NPAR  169
#define TB    128

// u64 pair-pack indices into swp[]: pack = (channel o, o+1) duplicated weights
#define OFF_W1F 0      // [c][opair]  8*4 = 32
#define OFF_W2  32     // [c][opair]  32
#define OFF_W1X 64     // [opair] 4
#define OFF_W1Y 68     // [opair] 4
#define OFF_B1  72     // [opair] 4
#define OFF_B2  76     // [opair] 4
#define NSWP    80

typedef unsigned long long u64;

__device__ float g_part[NINST * 8 * 3];   // per-(inst,band) partials
__device__ int   g_count[NINST];          // zero-init; finisher resets -> graph-safe

__constant__ float c_soi[6] = {64.f, 128.f, 256.f, 512.f, 1024.f, 2048.f};

// ---------- packed f32x2 helpers ----------
__device__ __forceinline__ u64 pk(float lo, float hi) {
    u64 r; asm("mov.b64 %0, {%1,%2};" : "=l"(r) : "f"(lo), "f"(hi)); return r;
}
__device__ __forceinline__ u64 dup(float x) {
    u64 r; asm("mov.b64 %0, {%1,%1};" : "=l"(r) : "f"(x)); return r;
}
__device__ __forceinline__ u64 fma2(u64 a, u64 b, u64 c) {
    u64 d; asm("fma.rn.f32x2 %0, %1, %2, %3;" : "=l"(d) : "l"(a), "l"(b), "l"(c)); return d;
}
union F2 { u64 u; float f[2]; };
__device__ __forceinline__ u64 relu2(u64 v) {
    F2 x; x.u = v;
    x.f[0] = fmaxf(x.f[0], 0.f);
    x.f[1] = fmaxf(x.f[1], 0.f);
    return x.u;
}
// un-hoistable smem loads (volatile): weights stay OUT of registers
// (prevents the reg=255 / occ=12% loop-invariant hoisting failure mode).
__device__ __forceinline__ float4 ldsv4(const float* p) {
    float4 v;
    unsigned a = (unsigned)__cvta_generic_to_shared(p);
    asm volatile("ld.shared.v4.b32 {%0,%1,%2,%3}, [%4];"
                 : "=f"(v.x), "=f"(v.y), "=f"(v.z), "=f"(v.w) : "r"(a));
    return v;
}
__device__ __forceinline__ void lds128(const u64* p, u64& a, u64& b) {
    unsigned ad = (unsigned)__cvta_generic_to_shared(p);
    asm volatile("ld.shared.v2.b64 {%0,%1}, [%2];" : "=l"(a), "=l"(b) : "r"(ad));
}

// ---------- single fused kernel: MLP + upsample + sigmoid + dice + finalize ----------
__global__ void __launch_bounds__(TB, 5) mask_kernel(
    const float* __restrict__ mf,
    const float* __restrict__ params,
    const float* __restrict__ iloc,
    const float* __restrict__ gt,
    const int*   __restrict__ im_inds,
    const int*   __restrict__ fpn,
    float*       __restrict__ out)
{
    const int b   = blockIdx.x;   // band 0..7 (17 input rows each)
    const int n   = blockIdx.y;   // instance
    const int tid = threadIdx.x;

    __shared__ __align__(16) u64   swp[NSWP];      // (o,o+1)-pair weight packs
    __shared__ __align__(16) float swf3[12];       // w3[8], b3, pad
    __shared__ __align__(16) float srxs[WWW];      // scalar relx per column
    __shared__ __align__(16) u64   sry[18];        // packed rely per band row
    __shared__ float sl[18 * WWW + 4];             // band logits (+pad)
    __shared__ float red[3][TB / 32];

    const int   im   = __ldg(&im_inds[n]);
    const float sinv = 1.f / c_soi[__ldg(&fpn[n])];
    const float locx = __ldg(&iloc[2 * n]);
    const float locy = __ldg(&iloc[2 * n + 1]);

    const int r0    = b * 17;
    const int nrows = min(18, HH - r0);            // 18, last band 17

    // scatter weights: paired layout (o,o+1) in u64 halves; w3/b3 scalar
    {
        float* swpf = (float*)swp;
        for (int i = tid; i < NPAR; i += TB) {
            float v = params[n * NPAR + i];
            if (i >= 144 && i < 152) { swf3[i - 144] = v; continue; }
            if (i == 168)            { swf3[8] = v;      continue; }
            int idx, half;
            if (i < 80) {                 // layer-1 weight: i = o*10 + k
                int o = i / 10, k = i - o * 10;
                half = o & 1;
                if      (k == 0) idx = OFF_W1X + (o >> 1);
                else if (k == 1) idx = OFF_W1Y + (o >> 1);
                else             idx = OFF_W1F + (k - 2) * 4 + (o >> 1);
            } else if (i < 144) {         // layer-2: i-80 = o*8 + c
                int t = i - 80;
                int o = t >> 3, c = t & 7;
                idx = OFF_W2 + c * 4 + (o >> 1); half = o & 1;
            } else if (i < 160) {         // b1
                int o = i - 152; idx = OFF_B1 + (o >> 1); half = o & 1;
            } else {                      // b2
                int o = i - 160; idx = OFF_B2 + (o >> 1); half = o & 1;
            }
            swpf[2 * idx + half] = v;
        }
    }
    for (int x = tid; x < WWW; x += TB)
        srxs[x] = (locx - (float)(8 * x + 4)) * sinv;
    for (int r = tid; r < nrows; r += TB) {
        float ry = (locy - (float)(8 * (r0 + r) + 4)) * sinv;
        sry[r] = pk(ry, ry);
    }
    __syncthreads();

    const int nchunks = nrows * 50;                // 4-px chunks per band
    const float* fimg = mf + (size_t)im * 8 * HW;

    // ---- phase 1: logits; packs = (o,o+1) channel pairs per pixel ----
    for (int g = tid; g < nchunks; g += TB) {
        const int row = g / 50;
        const int cx  = g - row * 50;
        const int xb  = cx * 4;
        const float* fb = fimg + (r0 + row) * WWW + xb;

        u64 a[4][4];                               // [opair][px]
        // layer 1: bias + rel coords
        {
            float4 rx = ldsv4(&srxs[xb]);          // 16B aligned (xb%4==0)
            u64 xd[4] = { dup(rx.x), dup(rx.y), dup(rx.z), dup(rx.w) };
            u64 yd = sry[row];
            u64 wx[4], wy[4], bp[4];
            lds128(&swp[OFF_W1X], wx[0], wx[1]); lds128(&swp[OFF_W1X + 2], wx[2], wx[3]);
            lds128(&swp[OFF_W1Y], wy[0], wy[1]); lds128(&swp[OFF_W1Y + 2], wy[2], wy[3]);
            lds128(&swp[OFF_B1],  bp[0], bp[1]); lds128(&swp[OFF_B1  + 2], bp[2], bp[3]);
#pragma unroll
            for (int op = 0; op < 4; op++)
#pragma unroll
                for (int p = 0; p < 4; p++)
                    a[op][p] = fma2(wy[op], yd, fma2(wx[op], xd[p], bp[op]));
        }
        // feat channels, depth-1 rolling prefetch; weight pairs need NO dup
        float4 fc = *(const float4*)(fb);
#pragma unroll
        for (int c = 0; c < 8; c++) {
            float4 fn;
            if (c < 7) fn = *(const float4*)(fb + (size_t)(c + 1) * HW);
            u64 fd[4] = { dup(fc.x), dup(fc.y), dup(fc.z), dup(fc.w) };
            u64 w[4];
            lds128(&swp[OFF_W1F + c * 4],     w[0], w[1]);
            lds128(&swp[OFF_W1F + c * 4 + 2], w[2], w[3]);
#pragma unroll
            for (int op = 0; op < 4; op++)
#pragma unroll
                for (int p = 0; p < 4; p++)
                    a[op][p] = fma2(w[op], fd[p], a[op][p]);
            fc = fn;
        }
        u64 h[4][4];                               // [cpair][px]
#pragma unroll
        for (int op = 0; op < 4; op++)
#pragma unroll
            for (int p = 0; p < 4; p++) h[op][p] = relu2(a[op][p]);

        // layer 2 (reuse a; c=0 folds bias)
        {
            u64 bp[4];
            lds128(&swp[OFF_B2], bp[0], bp[1]); lds128(&swp[OFF_B2 + 2], bp[2], bp[3]);
#pragma unroll
            for (int c = 0; c < 8; c++) {
                u64 w[4];
                lds128(&swp[OFF_W2 + c * 4],     w[0], w[1]);
                lds128(&swp[OFF_W2 + c * 4 + 2], w[2], w[3]);
                u64 hd[4];
#pragma unroll
                for (int p = 0; p < 4; p++) {
                    F2 t; t.u = h[c >> 1][p];
                    hd[p] = dup(t.f[c & 1]);
                }
                if (c == 0) {
#pragma unroll
                    for (int op = 0; op < 4; op++)
#pragma unroll
                        for (int p = 0; p < 4; p++)
                            a[op][p] = fma2(w[op], hd[p], bp[op]);
                } else {
#pragma unroll
                    for (int op = 0; op < 4; op++)
#pragma unroll
                        for (int p = 0; p < 4; p++)
                            a[op][p] = fma2(w[op], hd[p], a[op][p]);
                }
            }
        }
#pragma unroll
        for (int op = 0; op < 4; op++)
#pragma unroll
            for (int p = 0; p < 4; p++) a[op][p] = relu2(a[op][p]);

        // layer 3: scalar per pixel
        {
            float4 w3a = ldsv4(&swf3[0]);
            float4 w3b = ldsv4(&swf3[4]);
            float4 b3v = ldsv4(&swf3[8]);          // .x = bias
            float vv[4];
#pragma unroll
            for (int p = 0; p < 4; p++) {
                F2 q0, q1, q2, q3;
                q0.u = a[0][p]; q1.u = a[1][p]; q2.u = a[2][p]; q3.u = a[3][p];
                float v = b3v.x;
                v = fmaf(w3a.x, q0.f[0], v); v = fmaf(w3a.y, q0.f[1], v);
                v = fmaf(w3a.z, q1.f[0], v); v = fmaf(w3a.w, q1.f[1], v);
                v = fmaf(w3b.x, q2.f[0], v); v = fmaf(w3b.y, q2.f[1], v);
                v = fmaf(w3b.z, q3.f[0], v); v = fmaf(w3b.w, q3.f[1], v);
                vv[p] = v;
            }
            *(float4*)&sl[row * WWW + xb] = make_float4(vv[0], vv[1], vv[2], vv[3]);
        }
    }
    __syncthreads();

    // ---- phase 2: upsample + sigmoid + dice (4 px / thread, float4 gt) ----
    const int i_start = (r0 * 271 + 134) / 135;
    const int i_end   = (b == 7) ? OH : ((r0 + 17) * 271 + 134) / 135;
    const float* gtb  = gt + (size_t)n * OH * OW;

    const int ngroups = (i_end - i_start) * (OW / 4);
    float aI = 0.f, aS = 0.f, aT = 0.f;
    for (int idx = tid; idx < ngroups; idx += TB) {
        const int ir = idx / (OW / 4);
        const int jg = (idx - ir * (OW / 4)) * 4;
        const int i  = i_start + ir;

        const float fy = (float)i * (135.f / 271.f);
        const int   y0 = (int)fy;
        const float wy = fy - (float)y0;
        int ly0 = y0 - r0;
        int ly1 = min(y0 + 1, 135) - r0;
        ly0 = max(0, min(ly0, nrows - 1));
        ly1 = max(0, min(ly1, nrows - 1));
        const float* sl0 = &sl[ly0 * WWW];
        const float* sl1 = &sl[ly1 * WWW];

        const float4 tq = *(const float4*)(gtb + (size_t)i * OW + jg);

#pragma unroll
        for (int k = 0; k < 4; k++) {
            const int j = jg + k;
            float fx = (float)j * (199.f / 399.f);
            int   x0 = (int)fx;
            float wx = fx - (float)x0;
            int   x1 = min(x0 + 1, 199);

            float t00 = sl0[x0], t01 = sl0[x1];
            float t10 = sl1[x0], t11 = sl1[x1];
            float top = t00 + (t01 - t00) * wx;
            float bot = t10 + (t11 - t10) * wx;
            float v   = top + (bot - top) * wy;

            float s = __fdividef(1.f, 1.f + __expf(-v));
            float t = (&tq.x)[k];

            aI = fmaf(s, t, aI);
            aS = fmaf(s, s, aS);
            aT += t;                               // t in {0,1}
        }
    }

#pragma unroll
    for (int off = 16; off > 0; off >>= 1) {
        aI += __shfl_down_sync(0xffffffffu, aI, off);
        aS += __shfl_down_sync(0xffffffffu, aS, off);
        aT += __shfl_down_sync(0xffffffffu, aT, off);
    }
    const int wid = tid >> 5, lane = tid & 31;
    if (lane == 0) { red[0][wid] = aI; red[1][wid] = aS; red[2][wid] = aT; }
    __syncthreads();

    // ---- phase 3: last band-block per instance finalizes the loss ----
    if (tid == 0) {
        float I = red[0][0] + red[0][1] + red[0][2] + red[0][3];
        float S = red[1][0] + red[1][1] + red[1][2] + red[1][3];
        float T = red[2][0] + red[2][1] + red[2][2] + red[2][3];
        float* gp = &g_part[(n * 8 + b) * 3];
        gp[0] = I; gp[1] = S; gp[2] = T;
        __threadfence();
        int old = atomicAdd(&g_count[n], 1);
        if (old == 7) {                 // last band of this instance
            __threadfence();
            float sI = 0.f, sS = 0.f, sT = 0.f;
#pragma unroll
            for (int k = 0; k < 8; k++) {
                const float* q = &g_part[(n * 8 + k) * 3];
                sI += q[0]; sS += q[1]; sT += q[2];
            }
            out[n] = 1.f - 2.f * sI / (sS + sT + 1e-5f);
            g_count[n] = 0;             // reset for next graph replay
        }
    }
}

extern "C" void kernel_launch(void* const* d_in, const int* in_sizes, int n_in,
                              void* d_out, int out_size) {
    const float* mf     = (const float*)d_in[0];
    const float* params = (const float*)d_in[1];
    const float* iloc   = (const float*)d_in[2];
    const float* gt     = (const float*)d_in[3];
    const int*   imi    = (const int*)d_in[4];
    const int*   fpn    = (const int*)d_in[5];
    float*       out    = (float*)d_out;

    dim3 grid(8, NINST);
    mask_kernel<<<grid, TB>>>(mf, params, iloc, gt, imi, fpn, out);
}

// round 17
// speedup vs baseline: 1.5436x; 1.5436x over previous
#include <cuda_runtime.h>

#define HH    136
#define WWW   200
#define HW    (HH*WWW)
#define OH    272
#define OW    400
#define NIMG  8
#define NINST 512
#define NPAR  169
#define TB    128

// transposed SCALAR weight layout in smem (float indices, 16B-aligned groups)
#define OFF_W1F 0      // [c][o]  64
#define OFF_W2  64     // [c][o]  64
#define OFF_W1X 128    // [o]      8
#define OFF_W1Y 136    // [o]      8
#define OFF_B1  144    // [o]      8
#define OFF_B2  152    // [o]      8
#define OFF_W3  160    // [c]      8
#define OFF_B3  168    // scalar   1

typedef unsigned long long u64;

__device__ float g_part[NINST * 8 * 3];   // per-(inst,band) partials
__device__ int   g_count[NINST];          // zero-init; finisher resets -> graph-safe

__constant__ float c_soi[6] = {64.f, 128.f, 256.f, 512.f, 1024.f, 2048.f};

// ---------- packed f32x2 helpers ----------
__device__ __forceinline__ u64 pk(float lo, float hi) {
    u64 r; asm("mov.b64 %0, {%1,%2};" : "=l"(r) : "f"(lo), "f"(hi)); return r;
}
__device__ __forceinline__ u64 dup(float x) {
    u64 r; asm("mov.b64 %0, {%1,%1};" : "=l"(r) : "f"(x)); return r;
}
__device__ __forceinline__ u64 fma2(u64 a, u64 b, u64 c) {
    u64 d; asm("fma.rn.f32x2 %0, %1, %2, %3;" : "=l"(d) : "l"(a), "l"(b), "l"(c)); return d;
}
union F2 { u64 u; float f[2]; };
__device__ __forceinline__ u64 relu2(u64 v) {
    F2 x; x.u = v;
    x.f[0] = fmaxf(x.f[0], 0.f);
    x.f[1] = fmaxf(x.f[1], 0.f);
    return x.u;
}
// un-hoistable scalar-weight loads: volatile keeps weights OUT of registers
// (prevents the reg=255 / occ=12% loop-invariant hoisting failure mode).
// v4 = 4 weights per 16B/lane -> half the crossbar bytes of duplicated packs.
__device__ __forceinline__ float4 ldsv4(const float* p) {
    float4 v;
    unsigned a = (unsigned)__cvta_generic_to_shared(p);
    asm volatile("ld.shared.v4.b32 {%0,%1,%2,%3}, [%4];"
                 : "=f"(v.x), "=f"(v.y), "=f"(v.z), "=f"(v.w) : "r"(a));
    return v;
}
__device__ __forceinline__ u64 lds64v(const u64* p) {
    u64 v;
    unsigned a = (unsigned)__cvta_generic_to_shared(p);
    asm volatile("ld.shared.b64 %0, [%1];" : "=l"(v) : "r"(a));
    return v;
}

// ---------- single fused kernel: MLP + upsample + sigmoid + dice + finalize ----------
__global__ void __launch_bounds__(TB, 5) mask_kernel(
    const float* __restrict__ mf,
    const float* __restrict__ params,
    const float* __restrict__ iloc,
    const float* __restrict__ gt,
    const int*   __restrict__ im_inds,
    const int*   __restrict__ fpn,
    float*       __restrict__ out)
{
    const int b   = blockIdx.x;   // band 0..7 (17 input rows each)
    const int n   = blockIdx.y;   // instance
    const int tid = threadIdx.x;

    __shared__ __align__(16) float swf[NPAR + 3];  // transposed scalar weights
    __shared__ __align__(16) float say[18 * 8];    // b1[o] + w1y[o]*rely(row)
    __shared__ __align__(16) u64 srx[WWW / 2];     // packed relx per pixel-pair
    __shared__ __align__(16) u64 srow[40];         // phase-2 per-row {wy, ly0/ly1 offsets}
    __shared__ float sl[18 * WWW];                 // band logits
    __shared__ float red[3][TB / 32];

    const int   im   = __ldg(&im_inds[n]);
    const float sinv = 1.f / c_soi[__ldg(&fpn[n])];
    const float locx = __ldg(&iloc[2 * n]);
    const float locy = __ldg(&iloc[2 * n + 1]);

    const int r0    = b * 17;
    const int nrows = min(18, HH - r0);            // 18, last band 17

    const int i_start = (r0 * 271 + 134) / 135;
    const int i_end   = (b == 7) ? OH : ((r0 + 17) * 271 + 134) / 135;

    // scatter weights (scalar) into transposed smem layout
    for (int i = tid; i < NPAR; i += TB) {
        float v = params[n * NPAR + i];
        int d;
        if (i < 80) {                 // layer-1 weight: i = o*10 + k
            int o = i / 10, k = i - o * 10;
            if      (k == 0) d = OFF_W1X + o;
            else if (k == 1) d = OFF_W1Y + o;
            else             d = OFF_W1F + (k - 2) * 8 + o;
        } else if (i < 144) {         // layer-2 weight: i-80 = o*8 + c
            int t = i - 80;
            int o = t >> 3, c = t & 7;
            d = OFF_W2 + c * 8 + o;
        } else if (i < 152) d = OFF_W3 + (i - 144);
        else if (i < 160)   d = OFF_B1 + (i - 152);
        else if (i < 168)   d = OFF_B2 + (i - 160);
        else                d = OFF_B3;
        swf[d] = v;
    }
    // say[r][o] = b1[o] + w1y[o] * rely(r0+r)
    for (int idx = tid; idx < nrows * 8; idx += TB) {
        int r = idx >> 3, o = idx & 7;
        float ry = (locy - (float)(8 * (r0 + r) + 4)) * sinv;
        say[idx] = __ldg(&params[n * NPAR + 152 + o])
                 + __ldg(&params[n * NPAR + o * 10 + 1]) * ry;
    }
    for (int xp = tid; xp < WWW / 2; xp += TB) {
        int x = 2 * xp;
        srx[xp] = pk((locx - (float)(8 * x + 4))  * sinv,
                     (locx - (float)(8 * x + 12)) * sinv);
    }
    // phase-2 per-output-row table
    for (int ir = tid; ir < i_end - i_start; ir += TB) {
        int i = i_start + ir;
        float fy = (float)i * (135.f / 271.f);
        int   y0 = (int)fy;
        float wy = fy - (float)y0;
        int ly0 = max(0, min(y0 - r0, nrows - 1));
        int ly1 = max(0, min(min(y0 + 1, 135) - r0, nrows - 1));
        F2 t;
        t.f[0] = wy;
        t.f[1] = __int_as_float((ly0 * WWW << 16) | (ly1 * WWW));
        srow[ir] = t.u;
    }
    __syncthreads();

    const int nchunks = nrows * 50;                // 4-px chunks per band
    const float* fimg = mf + (size_t)im * 8 * HW;

    // ---- phase 1: logits (4 px = 2 packs; scalar-v4 weights + dup) ----
    for (int g = tid; g < nchunks; g += TB) {
        const int row = g / 50;
        const int cx  = g - row * 50;
        const int xb  = cx * 4;
        const float* fb = fimg + (r0 + row) * WWW + xb;

        u64 acc[8][2];
        // layer 1: folded (b1 + w1y*rely) + w1x*relx
        {
            u64 xr0 = srx[cx * 2], xr1 = srx[cx * 2 + 1];
#pragma unroll
            for (int o = 0; o < 8; o += 4) {
                float4 ay = ldsv4(&say[row * 8 + o]);
                float4 wx = ldsv4(&swf[OFF_W1X + o]);
#pragma unroll
                for (int k = 0; k < 4; k++) {
                    u64 ak  = dup((&ay.x)[k]);
                    u64 wxk = dup((&wx.x)[k]);
                    acc[o + k][0] = fma2(wxk, xr0, ak);
                    acc[o + k][1] = fma2(wxk, xr1, ak);
                }
            }
        }
        // feat channels, depth-1 rolling prefetch; u64 views = zero pack movs
        ulonglong2 fc = *(const ulonglong2*)(fb);
#pragma unroll
        for (int c = 0; c < 8; c++) {
            ulonglong2 fn;
            if (c < 7) fn = *(const ulonglong2*)(fb + (size_t)(c + 1) * HW);
            u64 x0 = fc.x, x1 = fc.y;
#pragma unroll
            for (int o = 0; o < 8; o += 4) {
                float4 w = ldsv4(&swf[OFF_W1F + c * 8 + o]);
#pragma unroll
                for (int k = 0; k < 4; k++) {
                    u64 wk = dup((&w.x)[k]);
                    acc[o + k][0] = fma2(wk, x0, acc[o + k][0]);
                    acc[o + k][1] = fma2(wk, x1, acc[o + k][1]);
                }
            }
            fc = fn;
        }
        u64 h[8][2];
#pragma unroll
        for (int o = 0; o < 8; o++) {
            h[o][0] = relu2(acc[o][0]);
            h[o][1] = relu2(acc[o][1]);
        }

        // layer 2 (reuse acc)
#pragma unroll
        for (int o = 0; o < 8; o += 4) {
            float4 bb = ldsv4(&swf[OFF_B2 + o]);
#pragma unroll
            for (int k = 0; k < 4; k++) {
                u64 bk = dup((&bb.x)[k]);
                acc[o + k][0] = bk; acc[o + k][1] = bk;
            }
        }
#pragma unroll
        for (int c = 0; c < 8; c++) {
#pragma unroll
            for (int o = 0; o < 8; o += 4) {
                float4 w = ldsv4(&swf[OFF_W2 + c * 8 + o]);
#pragma unroll
                for (int k = 0; k < 4; k++) {
                    u64 wk = dup((&w.x)[k]);
                    acc[o + k][0] = fma2(wk, h[c][0], acc[o + k][0]);
                    acc[o + k][1] = fma2(wk, h[c][1], acc[o + k][1]);
                }
            }
        }

        // layer 3
        u64 ov0, ov1;
        {
            float4 b3 = ldsv4(&swf[OFF_B3]);       // .x = bias (16B-aligned slot)
            u64 bk = dup(b3.x);
            ov0 = bk; ov1 = bk;
        }
#pragma unroll
        for (int c = 0; c < 8; c += 4) {
            float4 w = ldsv4(&swf[OFF_W3 + c]);
#pragma unroll
            for (int k = 0; k < 4; k++) {
                u64 wk = dup((&w.x)[k]);
                ov0 = fma2(wk, relu2(acc[c + k][0]), ov0);
                ov1 = fma2(wk, relu2(acc[c + k][1]), ov1);
            }
        }
        u64* slp = (u64*)&sl[row * WWW + xb];      // 8B-aligned
        slp[0] = ov0; slp[1] = ov1;
    }
    __syncthreads();

    // ---- phase 2: upsample + sigmoid + dice (4 px / thread, float4 gt) ----
    const float* gtb = gt + (size_t)n * OH * OW;

    const int ngroups = (i_end - i_start) * (OW / 4);
    float aI = 0.f, aS = 0.f, aT = 0.f;
    for (int idx = tid; idx < ngroups; idx += TB) {
        const int ir = idx / (OW / 4);
        const int jg = (idx - ir * (OW / 4)) * 4;
        const int i  = i_start + ir;

        F2 rt; rt.u = lds64v(&srow[ir]);
        const float wy   = rt.f[0];
        const int   lpak = __float_as_int(rt.f[1]);
        const float* sl0 = &sl[lpak >> 16];
        const float* sl1 = &sl[lpak & 0xffff];

        const float4 tq = *(const float4*)(gtb + (size_t)i * OW + jg);

#pragma unroll
        for (int k = 0; k < 4; k++) {
            const int j = jg + k;
            float fx = (float)j * (199.f / 399.f);
            int   x0 = (int)fx;
            float wx = fx - (float)x0;
            int   x1 = min(x0 + 1, 199);

            float t00 = sl0[x0], t01 = sl0[x1];
            float t10 = sl1[x0], t11 = sl1[x1];
            float top = t00 + (t01 - t00) * wx;
            float bot = t10 + (t11 - t10) * wx;
            float v   = top + (bot - top) * wy;

            float s = __fdividef(1.f, 1.f + __expf(-v));
            float t = (&tq.x)[k];

            aI = fmaf(s, t, aI);
            aS = fmaf(s, s, aS);
            aT += t;                               // t in {0,1}
        }
    }

#pragma unroll
    for (int off = 16; off > 0; off >>= 1) {
        aI += __shfl_down_sync(0xffffffffu, aI, off);
        aS += __shfl_down_sync(0xffffffffu, aS, off);
        aT += __shfl_down_sync(0xffffffffu, aT, off);
    }
    const int wid = tid >> 5, lane = tid & 31;
    if (lane == 0) { red[0][wid] = aI; red[1][wid] = aS; red[2][wid] = aT; }
    __syncthreads();

    // ---- phase 3: last band-block per instance finalizes the loss ----
    if (tid == 0) {
        float I = red[0][0] + red[0][1] + red[0][2] + red[0][3];
        float S = red[1][0] + red[1][1] + red[1][2] + red[1][3];
        float T = red[2][0] + red[2][1] + red[2][2] + red[2][3];
        float* gp = &g_part[(n * 8 + b) * 3];
        gp[0] = I; gp[1] = S; gp[2] = T;
        __threadfence();
        int old = atomicAdd(&g_count[n], 1);
        if (old == 7) {                 // last band of this instance
            __threadfence();
            float sI = 0.f, sS = 0.f, sT = 0.f;
#pragma unroll
            for (int k = 0; k < 8; k++) {
                const float* q = &g_part[(n * 8 + k) * 3];
                sI += q[0]; sS += q[1]; sT += q[2];
            }
            out[n] = 1.f - 2.f * sI / (sS + sT + 1e-5f);
            g_count[n] = 0;             // reset for next graph replay
        }
    }
}

extern "C" void kernel_launch(void* const* d_in, const int* in_sizes, int n_in,
                              void* d_out, int out_size) {
    const float* mf     = (const float*)d_in[0];
    const float* params = (const float*)d_in[1];
    const float* iloc   = (const float*)d_in[2];
    const float* gt     = (const float*)d_in[3];
    const int*   imi    = (const int*)d_in[4];
    const int*   fpn    = (const int*)d_in[5];
    float*       out    = (float*)d_out;

    dim3 grid(8, NINST);
    mask_kernel<<<grid, TB>>>(mf, params, iloc, gt, imi, fpn, out);
}